// round 16
// baseline (speedup 1.0000x reference)
#include <cuda_runtime.h>
#include <cuda_bf16.h>
#include <math.h>
#include <stdint.h>

#define B_    4
#define S_    2048
#define H_    768
#define NSEG  256
#define NROWS 2048
#define QPB   512
#define HALF  1024
#define KS_P  3
#define KS_S  12

#define SROW  24               // smem row stride in bf16 (16 data + 8 pad = 48B)
#define SLABE (128 * SROW)
#define SLAB64 (64 * SROW)
#define SMEM_MMA (2 * 4 * SLABE * 2)            // proj: 49152 B
#define SMEM_M64 (2 * 2 * (SLAB64 + SLABE) * 2) // sdot: 36864 B
#define NCONVW 576

// -------- scratch --------
__device__ __nv_bfloat16 g_A0[B_ * NSEG * H_];
__device__ __nv_bfloat16 g_A1[B_ * NSEG * H_];
__device__ __nv_bfloat16 g_W0[H_ * H_];
__device__ __nv_bfloat16 g_W1[H_ * H_];
__device__ __nv_bfloat16 g_P0[B_ * NSEG * H_];
__device__ __nv_bfloat16 g_P1[B_ * NSEG * H_];
__device__ float g_part [KS_P * B_ * NSEG * H_];
__device__ float g_spart[KS_S * B_ * NSEG * NSEG];
__device__ float g_sdot [B_ * NSEG * NSEG];
__device__ int   g_cnt  [B_ * NSEG];
__device__ int   g_first[B_ * NSEG];
__device__ float g_loss [NROWS];
__device__ int   g_corr [NROWS];

__device__ __forceinline__ void split2(float x, __nv_bfloat16& b0, __nv_bfloat16& b1) {
    b0 = __float2bfloat16(x);
    b1 = __float2bfloat16(x - __bfloat162float(b0));
}
union Pack4 { __nv_bfloat16 h[4]; unsigned long long u; };

__device__ __forceinline__ void mma16816(float* c,
                                         uint32_t a0, uint32_t a1, uint32_t a2, uint32_t a3,
                                         uint32_t b0, uint32_t b1) {
    asm volatile(
        "mma.sync.aligned.m16n8k16.row.col.f32.bf16.bf16.f32 "
        "{%0,%1,%2,%3}, {%4,%5,%6,%7}, {%8,%9}, {%0,%1,%2,%3};"
        : "+f"(c[0]), "+f"(c[1]), "+f"(c[2]), "+f"(c[3])
        : "r"(a0), "r"(a1), "r"(a2), "r"(a3), "r"(b0), "r"(b1));
}
__device__ __forceinline__ void ldsm4(uint32_t& d0, uint32_t& d1, uint32_t& d2,
                                      uint32_t& d3, const void* p) {
    uint32_t addr = (uint32_t)__cvta_generic_to_shared(p);
    asm volatile("ldmatrix.sync.aligned.m8n8.x4.shared.b16 {%0,%1,%2,%3}, [%4];"
                 : "=r"(d0), "=r"(d1), "=r"(d2), "=r"(d3) : "r"(addr));
}

// ---------------------------------------------------------------------------
// K1: fused prep — blocks [0,NCONVW): W->bf16x2; blocks >= NCONVW: segsum
// ---------------------------------------------------------------------------
__global__ __launch_bounds__(256) void k_prep(const float* __restrict__ x,
                                              const float* __restrict__ W,
                                              const int* __restrict__ ind) {
    if (blockIdx.x < NCONVW) {
        const int i = blockIdx.x * 256 + threadIdx.x;
        float4 w = ((const float4*)W)[i];
        Pack4 p0, p1;
        float a[4] = {w.x, w.y, w.z, w.w};
        #pragma unroll
        for (int j = 0; j < 4; j++) split2(a[j], p0.h[j], p1.h[j]);
        *(unsigned long long*)(g_W0 + (size_t)i * 4) = p0.u;
        *(unsigned long long*)(g_W1 + (size_t)i * 4) = p1.u;
        return;
    }
    const int sb = blockIdx.x - NCONVW;
    const int v = sb & (NSEG - 1);
    const int b = sb >> 8;
    const int t = threadIdx.x;
    if (t >= 192) return;
    const int* row = ind + b * S_;

    int lo, hi;
    { int l = 0, r = S_;
      while (l < r) { int m = (l + r) >> 1; if (row[m] < v) l = m + 1; else r = m; }
      lo = l; }
    { int l = lo, r = S_;
      while (l < r) { int m = (l + r) >> 1; if (row[m] <= v) l = m + 1; else r = m; }
      hi = l; }

    const int H4 = H_ / 4;
    float4 acc = make_float4(0.f, 0.f, 0.f, 0.f);
    const float4* xp = (const float4*)(x + ((size_t)b * S_ + lo) * H_) + t;

    int i = lo;
    for (; i + 8 <= hi; i += 8) {
        float4 u0 = xp[0];      float4 u1 = xp[H4];
        float4 u2 = xp[2 * H4]; float4 u3 = xp[3 * H4];
        float4 u4 = xp[4 * H4]; float4 u5 = xp[5 * H4];
        float4 u6 = xp[6 * H4]; float4 u7 = xp[7 * H4];
        xp += 8 * H4;
        acc.x += u0.x; acc.y += u0.y; acc.z += u0.z; acc.w += u0.w;
        acc.x += u1.x; acc.y += u1.y; acc.z += u1.z; acc.w += u1.w;
        acc.x += u2.x; acc.y += u2.y; acc.z += u2.z; acc.w += u2.w;
        acc.x += u3.x; acc.y += u3.y; acc.z += u3.z; acc.w += u3.w;
        acc.x += u4.x; acc.y += u4.y; acc.z += u4.z; acc.w += u4.w;
        acc.x += u5.x; acc.y += u5.y; acc.z += u5.z; acc.w += u5.w;
        acc.x += u6.x; acc.y += u6.y; acc.z += u6.z; acc.w += u6.w;
        acc.x += u7.x; acc.y += u7.y; acc.z += u7.z; acc.w += u7.w;
    }
    for (; i < hi; i++) {
        float4 u = *xp; xp += H4;
        acc.x += u.x; acc.y += u.y; acc.z += u.z; acc.w += u.w;
    }

    Pack4 p0, p1;
    float a[4] = {acc.x, acc.y, acc.z, acc.w};
    #pragma unroll
    for (int j = 0; j < 4; j++) split2(a[j], p0.h[j], p1.h[j]);
    const size_t e = ((size_t)b * NSEG + v) * H_ + t * 4;
    *(unsigned long long*)(g_A0 + e) = p0.u;
    *(unsigned long long*)(g_A1 + e) = p1.u;

    if (t == 0) {
        int lo2 = lo > HALF ? lo : HALF;
        int c   = hi - lo2; if (c < 0) c = 0;
        g_cnt  [b * NSEG + v] = c;
        g_first[b * NSEG + v] = lo2;
    }
}

// ---------------------------------------------------------------------------
// proj GEMM (M128 x N128): 3 cross terms, ldmatrix, reg-prefetch dbuf (R9)
// ---------------------------------------------------------------------------
__global__ __launch_bounds__(256) void k_proj_mma() {
    extern __shared__ __align__(16) __nv_bfloat16 sm[];
    const int ks = blockIdx.z;
    const int bm = blockIdx.y * 128;
    const int bn = blockIdx.x * 128;
    const int kb = ks * 256, ke = kb + 256;
    float* Cout = g_part + (size_t)ks * (B_ * NSEG * H_);

    const int tid  = threadIdx.x;
    const int wid  = tid >> 5, lane = tid & 31;
    const int wm   = wid & 1, wn = wid >> 1;
    const int gid  = lane >> 2, tid4 = lane & 3;
    const int lrow = tid >> 1;
    const int lhalf = (tid & 1) * 8;
    const int lml  = lane & 15;
    const int lmk  = (lane >> 4) * 8;

    const __nv_bfloat16* Ag[2] = {g_A0, g_A1};
    const __nv_bfloat16* Bg[2] = {g_W0, g_W1};

    float acc[4][4][4];
    #pragma unroll
    for (int i = 0; i < 4; i++)
        #pragma unroll
        for (int j = 0; j < 4; j++)
            #pragma unroll
            for (int k = 0; k < 4; k++) acc[i][j][k] = 0.f;

    uint4 ra[2], rb[2];
    #pragma unroll
    for (int s = 0; s < 2; s++) {
        ra[s] = *(const uint4*)(Ag[s] + (size_t)(bm + lrow) * H_ + kb + lhalf);
        rb[s] = *(const uint4*)(Bg[s] + (size_t)(bn + lrow) * H_ + kb + lhalf);
    }

    int stage = 0;
    for (int k0 = kb; k0 < ke; k0 += 16) {
        __nv_bfloat16* base = sm + stage * 4 * SLABE;
        #pragma unroll
        for (int s = 0; s < 2; s++) {
            *(uint4*)(base + s * SLABE + lrow * SROW + lhalf)       = ra[s];
            *(uint4*)(base + (2 + s) * SLABE + lrow * SROW + lhalf) = rb[s];
        }
        __syncthreads();

        if (k0 + 16 < ke) {
            #pragma unroll
            for (int s = 0; s < 2; s++) {
                ra[s] = *(const uint4*)(Ag[s] + (size_t)(bm + lrow) * H_ + k0 + 16 + lhalf);
                rb[s] = *(const uint4*)(Bg[s] + (size_t)(bn + lrow) * H_ + k0 + 16 + lhalf);
            }
        }

        uint32_t af[2][4][4];
        #pragma unroll
        for (int s = 0; s < 2; s++) {
            const __nv_bfloat16* As_ = base + s * SLABE;
            #pragma unroll
            for (int mi = 0; mi < 4; mi++) {
                const __nv_bfloat16* p = As_ + (wm * 64 + mi * 16 + lml) * SROW + lmk;
                ldsm4(af[s][mi][0], af[s][mi][1], af[s][mi][2], af[s][mi][3], p);
            }
        }
        uint32_t bfr[2][4][2];
        #pragma unroll
        for (int s = 0; s < 2; s++) {
            const __nv_bfloat16* Bs_ = base + (2 + s) * SLABE;
            #pragma unroll
            for (int h = 0; h < 2; h++) {
                const __nv_bfloat16* p = Bs_ + (wn * 32 + h * 16 + lml) * SROW + lmk;
                ldsm4(bfr[s][h * 2 + 0][0], bfr[s][h * 2 + 1][0],
                      bfr[s][h * 2 + 0][1], bfr[s][h * 2 + 1][1], p);
            }
        }
        #pragma unroll
        for (int mi = 0; mi < 4; mi++)
            #pragma unroll
            for (int ni = 0; ni < 4; ni++) {
                mma16816(acc[mi][ni], af[0][mi][0], af[0][mi][1], af[0][mi][2], af[0][mi][3],
                         bfr[0][ni][0], bfr[0][ni][1]);
                mma16816(acc[mi][ni], af[0][mi][0], af[0][mi][1], af[0][mi][2], af[0][mi][3],
                         bfr[1][ni][0], bfr[1][ni][1]);
                mma16816(acc[mi][ni], af[1][mi][0], af[1][mi][1], af[1][mi][2], af[1][mi][3],
                         bfr[0][ni][0], bfr[0][ni][1]);
            }
        __syncthreads();
        stage ^= 1;
    }

    #pragma unroll
    for (int mi = 0; mi < 4; mi++) {
        int r0 = bm + wm * 64 + mi * 16 + gid;
        #pragma unroll
        for (int ni = 0; ni < 4; ni++) {
            int c = bn + wn * 32 + ni * 8 + tid4 * 2;
            *(float2*)(Cout + (size_t)r0 * H_ + c)       = make_float2(acc[mi][ni][0], acc[mi][ni][1]);
            *(float2*)(Cout + (size_t)(r0 + 8) * H_ + c) = make_float2(acc[mi][ni][2], acc[mi][ni][3]);
        }
    }
}

// K2b: segproj = tanh(sum of 3 partials + bias) -> bf16x2 (2 float4/thread)
__global__ __launch_bounds__(256) void k_proj_fix(const float* __restrict__ bias) {
    #pragma unroll
    for (int u = 0; u < 2; u++) {
        const int i = blockIdx.x * 512 + u * 256 + threadIdx.x;
        const int c4 = i % (H_ / 4);
        float4 p0 = ((const float4*)g_part)[i];
        float4 p1 = ((const float4*)g_part)[i + 196608];
        float4 p2 = ((const float4*)g_part)[i + 393216];
        float4 bv = ((const float4*)bias)[c4];
        float o[4];
        o[0] = tanhf(p0.x + p1.x + p2.x + bv.x);
        o[1] = tanhf(p0.y + p1.y + p2.y + bv.y);
        o[2] = tanhf(p0.z + p1.z + p2.z + bv.z);
        o[3] = tanhf(p0.w + p1.w + p2.w + bv.w);
        Pack4 e0, e1;
        #pragma unroll
        for (int j = 0; j < 4; j++) split2(o[j], e0.h[j], e1.h[j]);
        *(unsigned long long*)(g_P0 + (size_t)i * 4) = e0.u;
        *(unsigned long long*)(g_P1 + (size_t)i * 4) = e1.u;
    }
}

// ---------------------------------------------------------------------------
// sdot GEMM (M64 x N128): R9-exact + column pruning by vmin = ind[b, HALF]
// (columns v < vmin have cnt==0 and are never read; label column handled
//  directly in k_rows)
// ---------------------------------------------------------------------------
__global__ __launch_bounds__(256) void k_sdot_mma(const int* __restrict__ ind) {
    extern __shared__ __align__(16) __nv_bfloat16 sm[];
    const int b  = blockIdx.z / KS_S;
    const int ks = blockIdx.z % KS_S;
    const int bm = blockIdx.y * 64;
    const int bn = blockIdx.x * 128;
    const int qmax = ind[b * S_ + QPB - 1];
    if (bm > qmax) return;
    const int vmin = ind[b * S_ + HALF];
    if (bn + 128 <= vmin) return;          // whole column tile masked

    const size_t po = (size_t)b * NSEG * H_;
    const __nv_bfloat16* Ag[2] = {g_P0 + po, g_P1 + po};
    float* Cout = g_spart + (size_t)(b * KS_S + ks) * (NSEG * NSEG);
    const int kb = ks * 64, ke = kb + 64;

    const int tid  = threadIdx.x;
    const int wid  = tid >> 5, lane = tid & 31;
    const int wm   = wid & 1, wn = wid >> 1;
    const int gid  = lane >> 2, tid4 = lane & 3;
    const int lml  = lane & 15;
    const int lmk  = (lane >> 4) * 8;
    const int a_s = tid >> 7, a_r = (tid >> 1) & 63, a_h = (tid & 1) * 8;
    const int stagesz = 2 * SLAB64 + 2 * SLABE;

    float acc[2][4][4];
    #pragma unroll
    for (int i = 0; i < 2; i++)
        #pragma unroll
        for (int j = 0; j < 4; j++)
            #pragma unroll
            for (int k = 0; k < 4; k++) acc[i][j][k] = 0.f;

    uint4 ra, rb[2];
    ra = *(const uint4*)(Ag[a_s] + (size_t)(bm + a_r) * H_ + kb + a_h);
    #pragma unroll
    for (int it = 0; it < 2; it++) {
        int i = tid + it * 256;
        int s = i >> 8, rem = i & 255, r = rem >> 1, h = (rem & 1) * 8;
        rb[it] = *(const uint4*)(Ag[s] + (size_t)(bn + r) * H_ + kb + h);
    }

    int stage = 0;
    for (int k0 = kb; k0 < ke; k0 += 16) {
        __nv_bfloat16* base = sm + stage * stagesz;
        *(uint4*)(base + a_s * SLAB64 + a_r * SROW + a_h) = ra;
        #pragma unroll
        for (int it = 0; it < 2; it++) {
            int i = tid + it * 256;
            int s = i >> 8, rem = i & 255, r = rem >> 1, h = (rem & 1) * 8;
            *(uint4*)(base + 2 * SLAB64 + s * SLABE + r * SROW + h) = rb[it];
        }
        __syncthreads();

        if (k0 + 16 < ke) {
            ra = *(const uint4*)(Ag[a_s] + (size_t)(bm + a_r) * H_ + k0 + 16 + a_h);
            #pragma unroll
            for (int it = 0; it < 2; it++) {
                int i = tid + it * 256;
                int s = i >> 8, rem = i & 255, r = rem >> 1, h = (rem & 1) * 8;
                rb[it] = *(const uint4*)(Ag[s] + (size_t)(bn + r) * H_ + k0 + 16 + h);
            }
        }

        uint32_t af[2][2][4];
        #pragma unroll
        for (int s = 0; s < 2; s++) {
            const __nv_bfloat16* As_ = base + s * SLAB64;
            #pragma unroll
            for (int mi = 0; mi < 2; mi++) {
                const __nv_bfloat16* p = As_ + (wm * 32 + mi * 16 + lml) * SROW + lmk;
                ldsm4(af[s][mi][0], af[s][mi][1], af[s][mi][2], af[s][mi][3], p);
            }
        }
        uint32_t bfr[2][4][2];
        #pragma unroll
        for (int s = 0; s < 2; s++) {
            const __nv_bfloat16* Bs_ = base + 2 * SLAB64 + s * SLABE;
            #pragma unroll
            for (int h = 0; h < 2; h++) {
                const __nv_bfloat16* p = Bs_ + (wn * 32 + h * 16 + lml) * SROW + lmk;
                ldsm4(bfr[s][h * 2 + 0][0], bfr[s][h * 2 + 1][0],
                      bfr[s][h * 2 + 0][1], bfr[s][h * 2 + 1][1], p);
            }
        }
        #pragma unroll
        for (int mi = 0; mi < 2; mi++)
            #pragma unroll
            for (int ni = 0; ni < 4; ni++) {
                mma16816(acc[mi][ni], af[0][mi][0], af[0][mi][1], af[0][mi][2], af[0][mi][3],
                         bfr[0][ni][0], bfr[0][ni][1]);
                mma16816(acc[mi][ni], af[0][mi][0], af[0][mi][1], af[0][mi][2], af[0][mi][3],
                         bfr[1][ni][0], bfr[1][ni][1]);
                mma16816(acc[mi][ni], af[1][mi][0], af[1][mi][1], af[1][mi][2], af[1][mi][3],
                         bfr[0][ni][0], bfr[0][ni][1]);
            }
        __syncthreads();
        stage ^= 1;
    }

    #pragma unroll
    for (int mi = 0; mi < 2; mi++) {
        int r0 = bm + wm * 32 + mi * 16 + gid;
        #pragma unroll
        for (int ni = 0; ni < 4; ni++) {
            int c = bn + wn * 32 + ni * 8 + tid4 * 2;
            *(float2*)(Cout + (size_t)r0 * NSEG + c)       = make_float2(acc[mi][ni][0], acc[mi][ni][1]);
            *(float2*)(Cout + (size_t)(r0 + 8) * NSEG + c) = make_float2(acc[mi][ni][2], acc[mi][ni][3]);
        }
    }
}

// K3b: g_sdot = sum of KS_S partials (pruned rows AND columns). grid (64, B)
__global__ __launch_bounds__(256) void k_sdot_fix(const int* __restrict__ ind) {
    const int b    = blockIdx.y;
    const int qmax = ind[b * S_ + QPB - 1];
    const int vmin = ind[b * S_ + HALF];
    const int row  = blockIdx.x * 4 + (threadIdx.x >> 6);
    if (row > qmax) return;
    const int c4   = threadIdx.x & 63;
    if ((c4 + 1) * 4 <= vmin) return;      // fully masked column chunk
    const size_t e = (size_t)row * 64 + c4;
    const size_t base = (size_t)b * KS_S * (NSEG * NSEG / 4);
    float4 s = make_float4(0.f, 0.f, 0.f, 0.f);
    #pragma unroll
    for (int ks = 0; ks < KS_S; ks++) {
        float4 p = ((const float4*)g_spart)[base + (size_t)ks * (NSEG * NSEG / 4) + e];
        s.x += p.x; s.y += p.y; s.z += p.z; s.w += p.w;
    }
    ((float4*)(g_sdot + (size_t)b * NSEG * NSEG))[e] = s;
}

// ---------------------------------------------------------------------------
// K4: per query row: masked logsumexp + argmax; slab computed DIRECTLY from
// P splits (label column may lie in the pruned region of g_sdot).
// ---------------------------------------------------------------------------
__global__ __launch_bounds__(256) void k_rows(const int* __restrict__ ind,
                                              const int* __restrict__ clc) {
    __shared__ __align__(16) int s_cnt[NSEG];
    __shared__ __align__(16) int s_fst[NSEG];
    const int lane = threadIdx.x & 31;
    const int gw   = blockIdx.x * 8 + (threadIdx.x >> 5);
    const int b    = gw >> 9;
    const int i    = gw & (QPB - 1);

    if (threadIdx.x < NSEG) {
        s_cnt[threadIdx.x] = g_cnt  [b * NSEG + threadIdx.x];
        s_fst[threadIdx.x] = g_first[b * NSEG + threadIdx.x];
    }
    __syncthreads();

    const int q     = ind[b * S_ + i];
    const int label = clc[b * S_ + i];
    const float* srow = g_sdot + ((size_t)b * NSEG + q) * NSEG;

    float s[8]; int c[8]; int f[8];
    #pragma unroll
    for (int t = 0; t < 2; t++) {
        int v4 = lane + 32 * t;
        float4 sv = __ldg((const float4*)srow + v4);
        int4   cv = ((const int4*)s_cnt)[v4];
        int4   fv = ((const int4*)s_fst)[v4];
        s[4 * t + 0] = sv.x; s[4 * t + 1] = sv.y; s[4 * t + 2] = sv.z; s[4 * t + 3] = sv.w;
        c[4 * t + 0] = cv.x; c[4 * t + 1] = cv.y; c[4 * t + 2] = cv.z; c[4 * t + 3] = cv.w;
        f[4 * t + 0] = fv.x; f[4 * t + 1] = fv.y; f[4 * t + 2] = fv.z; f[4 * t + 3] = fv.w;
    }

    // direct slab: dot(P[q], P[vlab]) with the same 3 bf16x2 cross terms
    const int vlab = ind[b * S_ + label];
    const size_t po = (size_t)b * NSEG * H_;
    const __nv_bfloat16* p0q = g_P0 + po + (size_t)q    * H_;
    const __nv_bfloat16* p1q = g_P1 + po + (size_t)q    * H_;
    const __nv_bfloat16* p0v = g_P0 + po + (size_t)vlab * H_;
    const __nv_bfloat16* p1v = g_P1 + po + (size_t)vlab * H_;
    float slab = 0.f;
    #pragma unroll
    for (int t = 0; t < 6; t++) {
        int k = t * 128 + lane * 4;
        Pack4 a0, a1, b0, b1;
        a0.u = *(const unsigned long long*)(p0q + k);
        a1.u = *(const unsigned long long*)(p1q + k);
        b0.u = *(const unsigned long long*)(p0v + k);
        b1.u = *(const unsigned long long*)(p1v + k);
        #pragma unroll
        for (int j = 0; j < 4; j++) {
            float fa0 = __bfloat162float(a0.h[j]);
            float fa1 = __bfloat162float(a1.h[j]);
            float fb0 = __bfloat162float(b0.h[j]);
            float fb1 = __bfloat162float(b1.h[j]);
            slab = fmaf(fa0, fb0 + fb1, slab);
            slab = fmaf(fa1, fb0, slab);
        }
    }
    #pragma unroll
    for (int off = 16; off; off >>= 1)
        slab += __shfl_xor_sync(0xffffffffu, slab, off);

    float bmax = -INFINITY; int bj = 0x7fffffff;
    #pragma unroll
    for (int t = 0; t < 8; t++) {
        if (c[t] > 0) {
            if (s[t] > bmax || (s[t] == bmax && f[t] < bj)) { bmax = s[t]; bj = f[t]; }
        }
    }
    #pragma unroll
    for (int off = 16; off; off >>= 1) {
        float os = __shfl_xor_sync(0xffffffffu, bmax, off);
        int   oj = __shfl_xor_sync(0xffffffffu, bj,   off);
        if (os > bmax || (os == bmax && oj < bj)) { bmax = os; bj = oj; }
    }

    float z = 0.0f;
    #pragma unroll
    for (int t = 0; t < 8; t++)
        if (c[t] > 0) z += (float)c[t] * expf(s[t] - bmax);
    #pragma unroll
    for (int off = 16; off; off >>= 1)
        z += __shfl_xor_sync(0xffffffffu, z, off);

    if (lane == 0) {
        float loss = (logf(z) + bmax) - slab;
        if (label < HALF) loss += 1.0e9f;
        g_loss[gw] = loss;
        g_corr[gw] = (bj == label) ? 1 : 0;
    }
}

// ---------------------------------------------------------------------------
// K5: final reduction -> 6 scalars
// ---------------------------------------------------------------------------
__global__ __launch_bounds__(256) void k_final(float* __restrict__ out) {
    __shared__ double sls[256], slt[256];
    __shared__ int    scs[256], sct[256];
    const int t = threadIdx.x;
    double ls = 0.0, lt = 0.0;
    int cs = 0, ct = 0;
    for (int r = t; r < NROWS; r += 256) {
        if (r & 1) { lt += (double)g_loss[r]; ct += g_corr[r]; }
        else       { ls += (double)g_loss[r]; cs += g_corr[r]; }
    }
    sls[t] = ls; slt[t] = lt; scs[t] = cs; sct[t] = ct;
    __syncthreads();
    for (int off = 128; off; off >>= 1) {
        if (t < off) {
            sls[t] += sls[t + off]; slt[t] += slt[t + off];
            scs[t] += scs[t + off]; sct[t] += sct[t + off];
        }
        __syncthreads();
    }
    if (t == 0) {
        const double n = (double)(NROWS / 2);
        out[0] = (float)(sls[0] / n);
        out[1] = (float)scs[0];
        out[2] = (float)(n + 1e-6);
        out[3] = (float)(slt[0] / n);
        out[4] = (float)sct[0];
        out[5] = (float)(n + 1e-6);
    }
}

// ---------------------------------------------------------------------------
extern "C" void kernel_launch(void* const* d_in, const int* in_sizes, int n_in,
                              void* d_out, int out_size) {
    const float* x    = (const float*)d_in[0];
    const float* W    = (const float*)d_in[1];
    const float* bias = (const float*)d_in[2];
    const int*   ind  = (const int*)  d_in[3];
    const int*   clc  = (const int*)  d_in[4];
    float* out = (float*)d_out;
    (void)in_sizes; (void)n_in; (void)out_size;

    static bool attr_set = false;
    if (!attr_set) {
        cudaFuncSetAttribute(k_proj_mma, cudaFuncAttributeMaxDynamicSharedMemorySize, SMEM_MMA);
        cudaFuncSetAttribute(k_sdot_mma, cudaFuncAttributeMaxDynamicSharedMemorySize, SMEM_M64);
        attr_set = true;
    }

    k_prep<<<NCONVW + NSEG * B_, 256>>>(x, W, ind);

    dim3 g2(H_ / 128, (B_ * NSEG) / 128, KS_P);      // (6, 8, 3) = 144 blocks
    k_proj_mma<<<g2, 256, SMEM_MMA>>>();
    k_proj_fix<<<(B_ * NSEG * H_ / 4) / 512, 256>>>(bias);

    dim3 g3(NSEG / 128, NSEG / 64, B_ * KS_S);       // (2, 4, 48)
    k_sdot_mma<<<g3, 256, SMEM_M64>>>(ind);
    dim3 g3f(64, B_);
    k_sdot_fix<<<g3f, 256>>>(ind);

    k_rows<<<NROWS / 8, 256>>>(ind, clc);

    k_final<<<1, 256>>>(out);
}

// round 17
// speedup vs baseline: 1.0477x; 1.0477x over previous
#include <cuda_runtime.h>
#include <cuda_bf16.h>
#include <math.h>
#include <stdint.h>

#define B_    4
#define S_    2048
#define H_    768
#define NSEG  256
#define NROWS 2048
#define QPB   512
#define HALF  1024
#define KS_P  3
#define KS_S  12

#define SROW  24               // smem row stride in bf16 (16 data + 8 pad = 48B)
#define SLABE (128 * SROW)
#define SLAB64 (64 * SROW)
#define SMEM_MMA (2 * 4 * SLABE * 2)            // proj: 49152 B
#define SMEM_M64 (2 * 2 * (SLAB64 + SLABE) * 2) // sdot: 36864 B
#define NCONVW 576

// -------- scratch --------
__device__ __nv_bfloat16 g_A0[B_ * NSEG * H_];
__device__ __nv_bfloat16 g_A1[B_ * NSEG * H_];
__device__ __nv_bfloat16 g_W0[H_ * H_];
__device__ __nv_bfloat16 g_W1[H_ * H_];
__device__ __nv_bfloat16 g_P0[B_ * NSEG * H_];
__device__ __nv_bfloat16 g_P1[B_ * NSEG * H_];
__device__ float g_part [KS_P * B_ * NSEG * H_];
__device__ float g_spart[KS_S * B_ * NSEG * NSEG];
__device__ float g_sdot [B_ * NSEG * NSEG];
__device__ int   g_cnt  [B_ * NSEG];
__device__ int   g_first[B_ * NSEG];
__device__ float g_loss [NROWS];
__device__ int   g_corr [NROWS];

__device__ __forceinline__ void split2(float x, __nv_bfloat16& b0, __nv_bfloat16& b1) {
    b0 = __float2bfloat16(x);
    b1 = __float2bfloat16(x - __bfloat162float(b0));
}
union Pack4 { __nv_bfloat16 h[4]; unsigned long long u; };

__device__ __forceinline__ void mma16816(float* c,
                                         uint32_t a0, uint32_t a1, uint32_t a2, uint32_t a3,
                                         uint32_t b0, uint32_t b1) {
    asm volatile(
        "mma.sync.aligned.m16n8k16.row.col.f32.bf16.bf16.f32 "
        "{%0,%1,%2,%3}, {%4,%5,%6,%7}, {%8,%9}, {%0,%1,%2,%3};"
        : "+f"(c[0]), "+f"(c[1]), "+f"(c[2]), "+f"(c[3])
        : "r"(a0), "r"(a1), "r"(a2), "r"(a3), "r"(b0), "r"(b1));
}
__device__ __forceinline__ void ldsm4(uint32_t& d0, uint32_t& d1, uint32_t& d2,
                                      uint32_t& d3, const void* p) {
    uint32_t addr = (uint32_t)__cvta_generic_to_shared(p);
    asm volatile("ldmatrix.sync.aligned.m8n8.x4.shared.b16 {%0,%1,%2,%3}, [%4];"
                 : "=r"(d0), "=r"(d1), "=r"(d2), "=r"(d3) : "r"(addr));
}

// ---------------------------------------------------------------------------
// K1: fused prep — blocks [0,NCONVW): W->bf16x2; blocks >= NCONVW: segsum
// ---------------------------------------------------------------------------
__global__ __launch_bounds__(256) void k_prep(const float* __restrict__ x,
                                              const float* __restrict__ W,
                                              const int* __restrict__ ind) {
    if (blockIdx.x < NCONVW) {
        const int i = blockIdx.x * 256 + threadIdx.x;
        float4 w = ((const float4*)W)[i];
        Pack4 p0, p1;
        float a[4] = {w.x, w.y, w.z, w.w};
        #pragma unroll
        for (int j = 0; j < 4; j++) split2(a[j], p0.h[j], p1.h[j]);
        *(unsigned long long*)(g_W0 + (size_t)i * 4) = p0.u;
        *(unsigned long long*)(g_W1 + (size_t)i * 4) = p1.u;
        return;
    }
    const int sb = blockIdx.x - NCONVW;
    const int v = sb & (NSEG - 1);
    const int b = sb >> 8;
    const int t = threadIdx.x;
    if (t >= 192) return;
    const int* row = ind + b * S_;

    int lo, hi;
    { int l = 0, r = S_;
      while (l < r) { int m = (l + r) >> 1; if (row[m] < v) l = m + 1; else r = m; }
      lo = l; }
    { int l = lo, r = S_;
      while (l < r) { int m = (l + r) >> 1; if (row[m] <= v) l = m + 1; else r = m; }
      hi = l; }

    const int H4 = H_ / 4;
    float4 acc = make_float4(0.f, 0.f, 0.f, 0.f);
    const float4* xp = (const float4*)(x + ((size_t)b * S_ + lo) * H_) + t;

    int i = lo;
    for (; i + 8 <= hi; i += 8) {
        float4 u0 = xp[0];      float4 u1 = xp[H4];
        float4 u2 = xp[2 * H4]; float4 u3 = xp[3 * H4];
        float4 u4 = xp[4 * H4]; float4 u5 = xp[5 * H4];
        float4 u6 = xp[6 * H4]; float4 u7 = xp[7 * H4];
        xp += 8 * H4;
        acc.x += u0.x; acc.y += u0.y; acc.z += u0.z; acc.w += u0.w;
        acc.x += u1.x; acc.y += u1.y; acc.z += u1.z; acc.w += u1.w;
        acc.x += u2.x; acc.y += u2.y; acc.z += u2.z; acc.w += u2.w;
        acc.x += u3.x; acc.y += u3.y; acc.z += u3.z; acc.w += u3.w;
        acc.x += u4.x; acc.y += u4.y; acc.z += u4.z; acc.w += u4.w;
        acc.x += u5.x; acc.y += u5.y; acc.z += u5.z; acc.w += u5.w;
        acc.x += u6.x; acc.y += u6.y; acc.z += u6.z; acc.w += u6.w;
        acc.x += u7.x; acc.y += u7.y; acc.z += u7.z; acc.w += u7.w;
    }
    for (; i < hi; i++) {
        float4 u = *xp; xp += H4;
        acc.x += u.x; acc.y += u.y; acc.z += u.z; acc.w += u.w;
    }

    Pack4 p0, p1;
    float a[4] = {acc.x, acc.y, acc.z, acc.w};
    #pragma unroll
    for (int j = 0; j < 4; j++) split2(a[j], p0.h[j], p1.h[j]);
    const size_t e = ((size_t)b * NSEG + v) * H_ + t * 4;
    *(unsigned long long*)(g_A0 + e) = p0.u;
    *(unsigned long long*)(g_A1 + e) = p1.u;

    if (t == 0) {
        int lo2 = lo > HALF ? lo : HALF;
        int c   = hi - lo2; if (c < 0) c = 0;
        g_cnt  [b * NSEG + v] = c;
        g_first[b * NSEG + v] = lo2;
    }
}

// ---------------------------------------------------------------------------
// proj GEMM (M128 x N128): 3 cross terms, ldmatrix, reg-prefetch dbuf (R9)
// ---------------------------------------------------------------------------
__global__ __launch_bounds__(256) void k_proj_mma() {
    extern __shared__ __align__(16) __nv_bfloat16 sm[];
    const int ks = blockIdx.z;
    const int bm = blockIdx.y * 128;
    const int bn = blockIdx.x * 128;
    const int kb = ks * 256, ke = kb + 256;
    float* Cout = g_part + (size_t)ks * (B_ * NSEG * H_);

    const int tid  = threadIdx.x;
    const int wid  = tid >> 5, lane = tid & 31;
    const int wm   = wid & 1, wn = wid >> 1;
    const int gid  = lane >> 2, tid4 = lane & 3;
    const int lrow = tid >> 1;
    const int lhalf = (tid & 1) * 8;
    const int lml  = lane & 15;
    const int lmk  = (lane >> 4) * 8;

    const __nv_bfloat16* Ag[2] = {g_A0, g_A1};
    const __nv_bfloat16* Bg[2] = {g_W0, g_W1};

    float acc[4][4][4];
    #pragma unroll
    for (int i = 0; i < 4; i++)
        #pragma unroll
        for (int j = 0; j < 4; j++)
            #pragma unroll
            for (int k = 0; k < 4; k++) acc[i][j][k] = 0.f;

    uint4 ra[2], rb[2];
    #pragma unroll
    for (int s = 0; s < 2; s++) {
        ra[s] = *(const uint4*)(Ag[s] + (size_t)(bm + lrow) * H_ + kb + lhalf);
        rb[s] = *(const uint4*)(Bg[s] + (size_t)(bn + lrow) * H_ + kb + lhalf);
    }

    int stage = 0;
    for (int k0 = kb; k0 < ke; k0 += 16) {
        __nv_bfloat16* base = sm + stage * 4 * SLABE;
        #pragma unroll
        for (int s = 0; s < 2; s++) {
            *(uint4*)(base + s * SLABE + lrow * SROW + lhalf)       = ra[s];
            *(uint4*)(base + (2 + s) * SLABE + lrow * SROW + lhalf) = rb[s];
        }
        __syncthreads();

        if (k0 + 16 < ke) {
            #pragma unroll
            for (int s = 0; s < 2; s++) {
                ra[s] = *(const uint4*)(Ag[s] + (size_t)(bm + lrow) * H_ + k0 + 16 + lhalf);
                rb[s] = *(const uint4*)(Bg[s] + (size_t)(bn + lrow) * H_ + k0 + 16 + lhalf);
            }
        }

        uint32_t af[2][4][4];
        #pragma unroll
        for (int s = 0; s < 2; s++) {
            const __nv_bfloat16* As_ = base + s * SLABE;
            #pragma unroll
            for (int mi = 0; mi < 4; mi++) {
                const __nv_bfloat16* p = As_ + (wm * 64 + mi * 16 + lml) * SROW + lmk;
                ldsm4(af[s][mi][0], af[s][mi][1], af[s][mi][2], af[s][mi][3], p);
            }
        }
        uint32_t bfr[2][4][2];
        #pragma unroll
        for (int s = 0; s < 2; s++) {
            const __nv_bfloat16* Bs_ = base + (2 + s) * SLABE;
            #pragma unroll
            for (int h = 0; h < 2; h++) {
                const __nv_bfloat16* p = Bs_ + (wn * 32 + h * 16 + lml) * SROW + lmk;
                ldsm4(bfr[s][h * 2 + 0][0], bfr[s][h * 2 + 1][0],
                      bfr[s][h * 2 + 0][1], bfr[s][h * 2 + 1][1], p);
            }
        }
        #pragma unroll
        for (int mi = 0; mi < 4; mi++)
            #pragma unroll
            for (int ni = 0; ni < 4; ni++) {
                mma16816(acc[mi][ni], af[0][mi][0], af[0][mi][1], af[0][mi][2], af[0][mi][3],
                         bfr[0][ni][0], bfr[0][ni][1]);
                mma16816(acc[mi][ni], af[0][mi][0], af[0][mi][1], af[0][mi][2], af[0][mi][3],
                         bfr[1][ni][0], bfr[1][ni][1]);
                mma16816(acc[mi][ni], af[1][mi][0], af[1][mi][1], af[1][mi][2], af[1][mi][3],
                         bfr[0][ni][0], bfr[0][ni][1]);
            }
        __syncthreads();
        stage ^= 1;
    }

    #pragma unroll
    for (int mi = 0; mi < 4; mi++) {
        int r0 = bm + wm * 64 + mi * 16 + gid;
        #pragma unroll
        for (int ni = 0; ni < 4; ni++) {
            int c = bn + wn * 32 + ni * 8 + tid4 * 2;
            *(float2*)(Cout + (size_t)r0 * H_ + c)       = make_float2(acc[mi][ni][0], acc[mi][ni][1]);
            *(float2*)(Cout + (size_t)(r0 + 8) * H_ + c) = make_float2(acc[mi][ni][2], acc[mi][ni][3]);
        }
    }
}

// K2b: segproj = tanh(sum of 3 partials + bias) -> bf16x2 (2 float4/thread)
__global__ __launch_bounds__(256) void k_proj_fix(const float* __restrict__ bias) {
    #pragma unroll
    for (int u = 0; u < 2; u++) {
        const int i = blockIdx.x * 512 + u * 256 + threadIdx.x;
        const int c4 = i % (H_ / 4);
        float4 p0 = ((const float4*)g_part)[i];
        float4 p1 = ((const float4*)g_part)[i + 196608];
        float4 p2 = ((const float4*)g_part)[i + 393216];
        float4 bv = ((const float4*)bias)[c4];
        float o[4];
        o[0] = tanhf(p0.x + p1.x + p2.x + bv.x);
        o[1] = tanhf(p0.y + p1.y + p2.y + bv.y);
        o[2] = tanhf(p0.z + p1.z + p2.z + bv.z);
        o[3] = tanhf(p0.w + p1.w + p2.w + bv.w);
        Pack4 e0, e1;
        #pragma unroll
        for (int j = 0; j < 4; j++) split2(o[j], e0.h[j], e1.h[j]);
        *(unsigned long long*)(g_P0 + (size_t)i * 4) = e0.u;
        *(unsigned long long*)(g_P1 + (size_t)i * 4) = e1.u;
    }
}

// ---------------------------------------------------------------------------
// sdot GEMM (M64 x N128): R9-exact, KS_S=12, rows pruned by qmax
// ---------------------------------------------------------------------------
__global__ __launch_bounds__(256) void k_sdot_mma(const int* __restrict__ ind) {
    extern __shared__ __align__(16) __nv_bfloat16 sm[];
    const int b  = blockIdx.z / KS_S;
    const int ks = blockIdx.z % KS_S;
    const int bm = blockIdx.y * 64;
    const int bn = blockIdx.x * 128;
    const int qmax = ind[b * S_ + QPB - 1];
    if (bm > qmax) return;

    const size_t po = (size_t)b * NSEG * H_;
    const __nv_bfloat16* Ag[2] = {g_P0 + po, g_P1 + po};
    float* Cout = g_spart + (size_t)(b * KS_S + ks) * (NSEG * NSEG);
    const int kb = ks * 64, ke = kb + 64;

    const int tid  = threadIdx.x;
    const int wid  = tid >> 5, lane = tid & 31;
    const int wm   = wid & 1, wn = wid >> 1;
    const int gid  = lane >> 2, tid4 = lane & 3;
    const int lml  = lane & 15;
    const int lmk  = (lane >> 4) * 8;
    const int a_s = tid >> 7, a_r = (tid >> 1) & 63, a_h = (tid & 1) * 8;
    const int stagesz = 2 * SLAB64 + 2 * SLABE;

    float acc[2][4][4];
    #pragma unroll
    for (int i = 0; i < 2; i++)
        #pragma unroll
        for (int j = 0; j < 4; j++)
            #pragma unroll
            for (int k = 0; k < 4; k++) acc[i][j][k] = 0.f;

    uint4 ra, rb[2];
    ra = *(const uint4*)(Ag[a_s] + (size_t)(bm + a_r) * H_ + kb + a_h);
    #pragma unroll
    for (int it = 0; it < 2; it++) {
        int i = tid + it * 256;
        int s = i >> 8, rem = i & 255, r = rem >> 1, h = (rem & 1) * 8;
        rb[it] = *(const uint4*)(Ag[s] + (size_t)(bn + r) * H_ + kb + h);
    }

    int stage = 0;
    for (int k0 = kb; k0 < ke; k0 += 16) {
        __nv_bfloat16* base = sm + stage * stagesz;
        *(uint4*)(base + a_s * SLAB64 + a_r * SROW + a_h) = ra;
        #pragma unroll
        for (int it = 0; it < 2; it++) {
            int i = tid + it * 256;
            int s = i >> 8, rem = i & 255, r = rem >> 1, h = (rem & 1) * 8;
            *(uint4*)(base + 2 * SLAB64 + s * SLABE + r * SROW + h) = rb[it];
        }
        __syncthreads();

        if (k0 + 16 < ke) {
            ra = *(const uint4*)(Ag[a_s] + (size_t)(bm + a_r) * H_ + k0 + 16 + a_h);
            #pragma unroll
            for (int it = 0; it < 2; it++) {
                int i = tid + it * 256;
                int s = i >> 8, rem = i & 255, r = rem >> 1, h = (rem & 1) * 8;
                rb[it] = *(const uint4*)(Ag[s] + (size_t)(bn + r) * H_ + k0 + 16 + h);
            }
        }

        uint32_t af[2][2][4];
        #pragma unroll
        for (int s = 0; s < 2; s++) {
            const __nv_bfloat16* As_ = base + s * SLAB64;
            #pragma unroll
            for (int mi = 0; mi < 2; mi++) {
                const __nv_bfloat16* p = As_ + (wm * 32 + mi * 16 + lml) * SROW + lmk;
                ldsm4(af[s][mi][0], af[s][mi][1], af[s][mi][2], af[s][mi][3], p);
            }
        }
        uint32_t bfr[2][4][2];
        #pragma unroll
        for (int s = 0; s < 2; s++) {
            const __nv_bfloat16* Bs_ = base + 2 * SLAB64 + s * SLABE;
            #pragma unroll
            for (int h = 0; h < 2; h++) {
                const __nv_bfloat16* p = Bs_ + (wn * 32 + h * 16 + lml) * SROW + lmk;
                ldsm4(bfr[s][h * 2 + 0][0], bfr[s][h * 2 + 1][0],
                      bfr[s][h * 2 + 0][1], bfr[s][h * 2 + 1][1], p);
            }
        }
        #pragma unroll
        for (int mi = 0; mi < 2; mi++)
            #pragma unroll
            for (int ni = 0; ni < 4; ni++) {
                mma16816(acc[mi][ni], af[0][mi][0], af[0][mi][1], af[0][mi][2], af[0][mi][3],
                         bfr[0][ni][0], bfr[0][ni][1]);
                mma16816(acc[mi][ni], af[0][mi][0], af[0][mi][1], af[0][mi][2], af[0][mi][3],
                         bfr[1][ni][0], bfr[1][ni][1]);
                mma16816(acc[mi][ni], af[1][mi][0], af[1][mi][1], af[1][mi][2], af[1][mi][3],
                         bfr[0][ni][0], bfr[0][ni][1]);
            }
        __syncthreads();
        stage ^= 1;
    }

    #pragma unroll
    for (int mi = 0; mi < 2; mi++) {
        int r0 = bm + wm * 32 + mi * 16 + gid;
        #pragma unroll
        for (int ni = 0; ni < 4; ni++) {
            int c = bn + wn * 32 + ni * 8 + tid4 * 2;
            *(float2*)(Cout + (size_t)r0 * NSEG + c)       = make_float2(acc[mi][ni][0], acc[mi][ni][1]);
            *(float2*)(Cout + (size_t)(r0 + 8) * NSEG + c) = make_float2(acc[mi][ni][2], acc[mi][ni][3]);
        }
    }
}

// K3b: g_sdot = sum of KS_S partials (pruned rows). grid (64, B)
__global__ __launch_bounds__(256) void k_sdot_fix(const int* __restrict__ ind) {
    const int b    = blockIdx.y;
    const int qmax = ind[b * S_ + QPB - 1];
    const int row  = blockIdx.x * 4 + (threadIdx.x >> 6);
    if (row > qmax) return;
    const int c4   = threadIdx.x & 63;
    const size_t e = (size_t)row * 64 + c4;
    const size_t base = (size_t)b * KS_S * (NSEG * NSEG / 4);
    float4 s = make_float4(0.f, 0.f, 0.f, 0.f);
    #pragma unroll
    for (int ks = 0; ks < KS_S; ks++) {
        float4 p = ((const float4*)g_spart)[base + (size_t)ks * (NSEG * NSEG / 4) + e];
        s.x += p.x; s.y += p.y; s.z += p.z; s.w += p.w;
    }
    ((float4*)(g_sdot + (size_t)b * NSEG * NSEG))[e] = s;
}

// ---------------------------------------------------------------------------
// K4: per query row: masked logsumexp + argmax over 256 segments (R9-exact)
// ---------------------------------------------------------------------------
__global__ __launch_bounds__(256) void k_rows(const int* __restrict__ ind,
                                              const int* __restrict__ clc) {
    __shared__ __align__(16) int s_cnt[NSEG];
    __shared__ __align__(16) int s_fst[NSEG];
    const int lane = threadIdx.x & 31;
    const int gw   = blockIdx.x * 8 + (threadIdx.x >> 5);
    const int b    = gw >> 9;
    const int i    = gw & (QPB - 1);

    if (threadIdx.x < NSEG) {
        s_cnt[threadIdx.x] = g_cnt  [b * NSEG + threadIdx.x];
        s_fst[threadIdx.x] = g_first[b * NSEG + threadIdx.x];
    }
    __syncthreads();

    const int q     = ind[b * S_ + i];
    const int label = clc[b * S_ + i];
    const float* srow = g_sdot + ((size_t)b * NSEG + q) * NSEG;

    float s[8]; int c[8]; int f[8];
    #pragma unroll
    for (int t = 0; t < 2; t++) {
        int v4 = lane + 32 * t;
        float4 sv = __ldg((const float4*)srow + v4);
        int4   cv = ((const int4*)s_cnt)[v4];
        int4   fv = ((const int4*)s_fst)[v4];
        s[4 * t + 0] = sv.x; s[4 * t + 1] = sv.y; s[4 * t + 2] = sv.z; s[4 * t + 3] = sv.w;
        c[4 * t + 0] = cv.x; c[4 * t + 1] = cv.y; c[4 * t + 2] = cv.z; c[4 * t + 3] = cv.w;
        f[4 * t + 0] = fv.x; f[4 * t + 1] = fv.y; f[4 * t + 2] = fv.z; f[4 * t + 3] = fv.w;
    }

    float bmax = -INFINITY; int bj = 0x7fffffff;
    #pragma unroll
    for (int t = 0; t < 8; t++) {
        if (c[t] > 0) {
            if (s[t] > bmax || (s[t] == bmax && f[t] < bj)) { bmax = s[t]; bj = f[t]; }
        }
    }
    #pragma unroll
    for (int off = 16; off; off >>= 1) {
        float os = __shfl_xor_sync(0xffffffffu, bmax, off);
        int   oj = __shfl_xor_sync(0xffffffffu, bj,   off);
        if (os > bmax || (os == bmax && oj < bj)) { bmax = os; bj = oj; }
    }

    float z = 0.0f;
    #pragma unroll
    for (int t = 0; t < 8; t++)
        if (c[t] > 0) z += (float)c[t] * expf(s[t] - bmax);
    #pragma unroll
    for (int off = 16; off; off >>= 1)
        z += __shfl_xor_sync(0xffffffffu, z, off);

    if (lane == 0) {
        int vlab = ind[b * S_ + label];
        float slab = __ldg(srow + vlab);
        float loss = (logf(z) + bmax) - slab;
        if (label < HALF) loss += 1.0e9f;
        g_loss[gw] = loss;
        g_corr[gw] = (bj == label) ? 1 : 0;
    }
}

// ---------------------------------------------------------------------------
// K5: final reduction -> 6 scalars
// ---------------------------------------------------------------------------
__global__ __launch_bounds__(256) void k_final(float* __restrict__ out) {
    __shared__ double sls[256], slt[256];
    __shared__ int    scs[256], sct[256];
    const int t = threadIdx.x;
    double ls = 0.0, lt = 0.0;
    int cs = 0, ct = 0;
    for (int r = t; r < NROWS; r += 256) {
        if (r & 1) { lt += (double)g_loss[r]; ct += g_corr[r]; }
        else       { ls += (double)g_loss[r]; cs += g_corr[r]; }
    }
    sls[t] = ls; slt[t] = lt; scs[t] = cs; sct[t] = ct;
    __syncthreads();
    for (int off = 128; off; off >>= 1) {
        if (t < off) {
            sls[t] += sls[t + off]; slt[t] += slt[t + off];
            scs[t] += scs[t + off]; sct[t] += sct[t + off];
        }
        __syncthreads();
    }
    if (t == 0) {
        const double n = (double)(NROWS / 2);
        out[0] = (float)(sls[0] / n);
        out[1] = (float)scs[0];
        out[2] = (float)(n + 1e-6);
        out[3] = (float)(slt[0] / n);
        out[4] = (float)sct[0];
        out[5] = (float)(n + 1e-6);
    }
}

// ---------------------------------------------------------------------------
extern "C" void kernel_launch(void* const* d_in, const int* in_sizes, int n_in,
                              void* d_out, int out_size) {
    const float* x    = (const float*)d_in[0];
    const float* W    = (const float*)d_in[1];
    const float* bias = (const float*)d_in[2];
    const int*   ind  = (const int*)  d_in[3];
    const int*   clc  = (const int*)  d_in[4];
    float* out = (float*)d_out;
    (void)in_sizes; (void)n_in; (void)out_size;

    static bool attr_set = false;
    if (!attr_set) {
        cudaFuncSetAttribute(k_proj_mma, cudaFuncAttributeMaxDynamicSharedMemorySize, SMEM_MMA);
        cudaFuncSetAttribute(k_sdot_mma, cudaFuncAttributeMaxDynamicSharedMemorySize, SMEM_M64);
        attr_set = true;
    }

    k_prep<<<NCONVW + NSEG * B_, 256>>>(x, W, ind);

    dim3 g2(H_ / 128, (B_ * NSEG) / 128, KS_P);      // (6, 8, 3) = 144 blocks
    k_proj_mma<<<g2, 256, SMEM_MMA>>>();
    k_proj_fix<<<(B_ * NSEG * H_ / 4) / 512, 256>>>(bias);

    dim3 g3(NSEG / 128, NSEG / 64, B_ * KS_S);       // (2, 4, 48)
    k_sdot_mma<<<g3, 256, SMEM_M64>>>(ind);
    dim3 g3f(64, B_);
    k_sdot_fix<<<g3f, 256>>>(ind);

    k_rows<<<NROWS / 8, 256>>>(ind, clc);

    k_final<<<1, 256>>>(out);
}